// round 9
// baseline (speedup 1.0000x reference)
#include <cuda_runtime.h>
#include <math.h>

// B=131072, D=512, N=1.
// loss_b = log1p(exp((dot(img,neg) - dot(img,pos)) / 50)); output = mean_b loss_b.
// Main: 4096 blocks x 1024 threads (32 warps), one row per warp (R6 body).
// Finalize: single block over 4096 partials (16 KB, L2-resident).

#define B_TOTAL 131072
#define D_F4 128              // 512 floats = 128 float4 per row
#define WARPS_PER_BLOCK 32
#define THREADS 1024
#define NBLOCKS (B_TOTAL / WARPS_PER_BLOCK)   // 4096

__device__ __align__(16) float g_partial[NBLOCKS];

__global__ __launch_bounds__(THREADS) void loss_main_kernel(
    const float4* __restrict__ img,
    const float4* __restrict__ pos,
    const float4* __restrict__ neg)
{
    const int wid  = threadIdx.x >> 5;
    const int lane = threadIdx.x & 31;
    const size_t row  = (size_t)blockIdx.x * WARPS_PER_BLOCK + wid;
    const size_t base = row * D_F4 + lane;

    float dp = 0.0f, dn = 0.0f;
#pragma unroll
    for (int i = 0; i < 4; i++) {
        const float4 a = __ldg(img + base + i * 32);
        const float4 p = __ldg(pos + base + i * 32);
        const float4 n = __ldg(neg + base + i * 32);
        dp += a.x * p.x + a.y * p.y + a.z * p.z + a.w * p.w;
        dn += a.x * n.x + a.y * n.y + a.z * n.z + a.w * n.w;
    }

#pragma unroll
    for (int off = 16; off; off >>= 1) {
        dp += __shfl_xor_sync(0xffffffffu, dp, off);
        dn += __shfl_xor_sync(0xffffffffu, dn, off);
    }

    __shared__ float s_loss[WARPS_PER_BLOCK];
    if (lane == 0) {
        // -log(ep/(ep+en)) == log1p(exp((dn-dp)/50))
        s_loss[wid] = log1pf(expf((dn - dp) * 0.02f));
    }
    __syncthreads();

    // warp 0 reduces the 32 per-warp losses via shuffle
    if (wid == 0) {
        float v = s_loss[lane];
#pragma unroll
        for (int off = 16; off; off >>= 1)
            v += __shfl_xor_sync(0xffffffffu, v, off);
        if (lane == 0) g_partial[blockIdx.x] = v;   // plain STG: no zero pass
    }
}

__global__ __launch_bounds__(256) void finalize_kernel(float* __restrict__ out) {
    const int wid  = threadIdx.x >> 5;
    const int lane = threadIdx.x & 31;

    const float4* p4 = (const float4*)g_partial;   // 1024 float4
    float acc = 0.0f;
#pragma unroll
    for (int i = 0; i < (NBLOCKS / 4) / 256; i++) {   // 4 iters
        float4 v = p4[threadIdx.x + i * 256];
        acc += v.x + v.y + v.z + v.w;
    }
#pragma unroll
    for (int off = 16; off; off >>= 1)
        acc += __shfl_xor_sync(0xffffffffu, acc, off);

    __shared__ float s_fin[8];
    if (lane == 0) s_fin[wid] = acc;
    __syncthreads();
    if (threadIdx.x == 0) {
        float tot = 0.0f;
#pragma unroll
        for (int i = 0; i < 8; i++) tot += s_fin[i];
        out[0] = tot / (float)B_TOTAL;
    }
}

extern "C" void kernel_launch(void* const* d_in, const int* in_sizes, int n_in,
                              void* d_out, int out_size) {
    (void)in_sizes; (void)n_in; (void)out_size;
    const float4* img = (const float4*)d_in[0];
    const float4* pos = (const float4*)d_in[1];
    const float4* neg = (const float4*)d_in[2];
    float* out = (float*)d_out;

    loss_main_kernel<<<NBLOCKS, THREADS>>>(img, pos, neg);
    finalize_kernel<<<1, 256>>>(out);
}

// round 10
// speedup vs baseline: 1.1485x; 1.1485x over previous
#include <cuda_runtime.h>
#include <math.h>

// B=131072, D=512, N=1.
// loss_b = log1p(exp((dot(img,neg) - dot(img,pos)) / 50)); output = mean_b loss_b.
// Main: grid 16384 x 256 (one row per warp, R6-best body), plain STG partials.
// Finalize: PDL-launched so its launch latency overlaps the main kernel;
//           cudaGridDependencySynchronize() gates the partial reads.

#define B_TOTAL 131072
#define D_F4 128              // 512 floats = 128 float4 per row
#define WARPS_PER_BLOCK 8
#define THREADS 256
#define NBLOCKS (B_TOTAL / WARPS_PER_BLOCK)   // 16384

__device__ __align__(16) float g_partial[NBLOCKS];

__global__ __launch_bounds__(THREADS) void loss_main_kernel(
    const float4* __restrict__ img,
    const float4* __restrict__ pos,
    const float4* __restrict__ neg)
{
    // Let the dependent (finalize) kernel begin its launch immediately;
    // it still waits on full grid completion at cudaGridDependencySynchronize().
    cudaTriggerProgrammaticLaunchCompletion();

    const int wid  = threadIdx.x >> 5;
    const int lane = threadIdx.x & 31;
    const size_t row  = (size_t)blockIdx.x * WARPS_PER_BLOCK + wid;
    const size_t base = row * D_F4 + lane;

    float dp = 0.0f, dn = 0.0f;
#pragma unroll
    for (int i = 0; i < 4; i++) {
        const float4 a = __ldg(img + base + i * 32);
        const float4 p = __ldg(pos + base + i * 32);
        const float4 n = __ldg(neg + base + i * 32);
        dp += a.x * p.x + a.y * p.y + a.z * p.z + a.w * p.w;
        dn += a.x * n.x + a.y * n.y + a.z * n.z + a.w * n.w;
    }

#pragma unroll
    for (int off = 16; off; off >>= 1) {
        dp += __shfl_xor_sync(0xffffffffu, dp, off);
        dn += __shfl_xor_sync(0xffffffffu, dn, off);
    }

    __shared__ float s_loss[WARPS_PER_BLOCK];
    if (lane == 0) {
        // -log(ep/(ep+en)) == log1p(exp((dn-dp)/50))
        s_loss[wid] = log1pf(expf((dn - dp) * 0.02f));
    }
    __syncthreads();

    if (threadIdx.x == 0) {
        float sum = 0.0f;
#pragma unroll
        for (int i = 0; i < WARPS_PER_BLOCK; i++) sum += s_loss[i];
        g_partial[blockIdx.x] = sum;          // plain STG: no zero pass needed
    }
}

__global__ __launch_bounds__(THREADS) void finalize_kernel(float* __restrict__ out) {
    // Wait until the upstream (main) grid's memory is fully visible.
    cudaGridDependencySynchronize();

    const int wid  = threadIdx.x >> 5;
    const int lane = threadIdx.x & 31;

    const float4* p4 = (const float4*)g_partial;   // 4096 float4
    float acc = 0.0f;
#pragma unroll
    for (int i = 0; i < (NBLOCKS / 4) / THREADS; i++) {   // 16 iters
        float4 v = p4[threadIdx.x + i * THREADS];
        acc += v.x + v.y + v.z + v.w;
    }
#pragma unroll
    for (int off = 16; off; off >>= 1)
        acc += __shfl_xor_sync(0xffffffffu, acc, off);

    __shared__ float s_fin[WARPS_PER_BLOCK];
    if (lane == 0) s_fin[wid] = acc;
    __syncthreads();
    if (threadIdx.x == 0) {
        float tot = 0.0f;
#pragma unroll
        for (int i = 0; i < WARPS_PER_BLOCK; i++) tot += s_fin[i];
        out[0] = tot / (float)B_TOTAL;
    }
}

extern "C" void kernel_launch(void* const* d_in, const int* in_sizes, int n_in,
                              void* d_out, int out_size) {
    (void)in_sizes; (void)n_in; (void)out_size;
    const float4* img = (const float4*)d_in[0];
    const float4* pos = (const float4*)d_in[1];
    const float4* neg = (const float4*)d_in[2];
    float* out = (float*)d_out;

    loss_main_kernel<<<NBLOCKS, THREADS>>>(img, pos, neg);

    // PDL launch of finalize: its launch overhead overlaps the main kernel.
    cudaLaunchConfig_t cfg = {};
    cfg.gridDim  = dim3(1, 1, 1);
    cfg.blockDim = dim3(THREADS, 1, 1);
    cfg.dynamicSmemBytes = 0;
    cudaLaunchAttribute attrs[1];
    attrs[0].id = cudaLaunchAttributeProgrammaticStreamSerialization;
    attrs[0].val.programmaticStreamSerializationAllowed = 1;
    cfg.attrs = attrs;
    cfg.numAttrs = 1;
    cudaLaunchKernelEx(&cfg, finalize_kernel, out);
}

// round 12
// speedup vs baseline: 1.1507x; 1.0019x over previous
#include <cuda_runtime.h>
#include <math.h>

// B=131072, D=512, N=1.
// loss_b = log1p(exp((dot(img,neg) - dot(img,pos)) / 50)); output = mean_b loss_b.
// Single kernel, R6-best streaming body. Block retirement = ONE acq_rel global
// atomic ticket (no __threadfence / MEMBAR). Last block reduces partials via
// __ldcg (L2-direct) and writes the mean. Ticket self-resets for graph replay.

#define B_TOTAL 131072
#define D_F4 128              // 512 floats = 128 float4 per row
#define WARPS_PER_BLOCK 8
#define THREADS 256
#define NBLOCKS (B_TOTAL / WARPS_PER_BLOCK)   // 16384

__device__ __align__(16) float g_partial[NBLOCKS];
__device__ unsigned int g_ticket = 0;   // last block resets to 0 each run

__device__ __forceinline__ unsigned int ticket_acq_rel(unsigned int* p) {
    unsigned int old;
    asm volatile("atom.acq_rel.gpu.global.add.u32 %0, [%1], 1;"
                 : "=r"(old) : "l"(p) : "memory");
    return old;
}

__global__ __launch_bounds__(THREADS) void loss_onekernel(
    const float4* __restrict__ img,
    const float4* __restrict__ pos,
    const float4* __restrict__ neg,
    float* __restrict__ out)
{
    const int wid  = threadIdx.x >> 5;
    const int lane = threadIdx.x & 31;
    const size_t row  = (size_t)blockIdx.x * WARPS_PER_BLOCK + wid;
    const size_t base = row * D_F4 + lane;

    float dp = 0.0f, dn = 0.0f;
#pragma unroll
    for (int i = 0; i < 4; i++) {
        const float4 a = __ldg(img + base + i * 32);
        const float4 p = __ldg(pos + base + i * 32);
        const float4 n = __ldg(neg + base + i * 32);
        dp += a.x * p.x + a.y * p.y + a.z * p.z + a.w * p.w;
        dn += a.x * n.x + a.y * n.y + a.z * n.z + a.w * n.w;
    }

#pragma unroll
    for (int off = 16; off; off >>= 1) {
        dp += __shfl_xor_sync(0xffffffffu, dp, off);
        dn += __shfl_xor_sync(0xffffffffu, dn, off);
    }

    __shared__ float s_loss[WARPS_PER_BLOCK];
    __shared__ bool  s_last;
    if (lane == 0) {
        // -log(ep/(ep+en)) == log1p(exp((dn-dp)/50))
        s_loss[wid] = log1pf(expf((dn - dp) * 0.02f));
    }
    __syncthreads();

    if (threadIdx.x == 0) {
        float sum = 0.0f;
#pragma unroll
        for (int i = 0; i < WARPS_PER_BLOCK; i++) sum += s_loss[i];
        g_partial[blockIdx.x] = sum;                    // plain STG (L2)
        // release orders the STG above before the ticket increment;
        // acquire makes all prior releases visible to the last block.
        s_last = (ticket_acq_rel(&g_ticket) == NBLOCKS - 1);
    }
    __syncthreads();

    if (s_last) {
        // Tail reduce: 64 KB of partials, L2-resident. __ldcg bypasses L1.
        float acc = 0.0f;
#pragma unroll
        for (int i = 0; i < (NBLOCKS / 4) / THREADS; i++) {   // 16 iters
            const float4* p = (const float4*)g_partial + threadIdx.x + i * THREADS;
            float4 v = __ldcg(p);
            acc += v.x + v.y + v.z + v.w;
        }
#pragma unroll
        for (int off = 16; off; off >>= 1)
            acc += __shfl_xor_sync(0xffffffffu, acc, off);

        __shared__ float s_fin[WARPS_PER_BLOCK];
        if (lane == 0) s_fin[wid] = acc;
        __syncthreads();
        if (threadIdx.x == 0) {
            float tot = 0.0f;
#pragma unroll
            for (int i = 0; i < WARPS_PER_BLOCK; i++) tot += s_fin[i];
            out[0] = tot / (float)B_TOTAL;
            g_ticket = 0;                   // reset for next graph replay
        }
    }
}

extern "C" void kernel_launch(void* const* d_in, const int* in_sizes, int n_in,
                              void* d_out, int out_size) {
    (void)in_sizes; (void)n_in; (void)out_size;
    const float4* img = (const float4*)d_in[0];
    const float4* pos = (const float4*)d_in[1];
    const float4* neg = (const float4*)d_in[2];
    float* out = (float*)d_out;

    loss_onekernel<<<NBLOCKS, THREADS>>>(img, pos, neg, out);
}